// round 15
// baseline (speedup 1.0000x reference)
#include <cuda_runtime.h>
#include <cstdint>

typedef unsigned long long ull;

#define B_  32
#define D_  1024
#define H_  1024
#define M_  2048
#define K3_ 3072

#define GRID_ 296          // 2 CTAs per SM

#define KS_ENC 16
#define KS_SIM 32
#define KS_INT 32
#define KS_OUT 32
#define MS_MT  32

// ---------------- scratch ----------------
__device__ float g_comb[K3_ * B_];              // [k][b]: 0..1023=z, 1024..2047=m_t, 2048..3071=prev_h
__device__ float g_zinv[B_];
__device__ float g_encp[KS_ENC * H_ * B_];
__device__ float g_zpre[H_ * B_];
__device__ float g_em[M_ * H_];                 // eff_mem [m][h]
__device__ float g_emT[H_ * M_];                // eff_mem transposed [h][m]
__device__ float g_ssqp[32 * M_];
__device__ float g_rss[M_];
__device__ float g_simp[KS_SIM * M_ * B_];
__device__ float g_sim[M_ * B_];
__device__ float g_attn[M_ * B_];
__device__ float g_mtp[MS_MT * H_ * B_];
__device__ float g_intp[KS_INT * K3_ * B_];
__device__ float g_hid[K3_ * B_];
__device__ float g_outp[KS_OUT * H_ * B_];
__device__ float g_opre[H_ * B_];

__device__ unsigned g_cnt = 0;
__device__ unsigned g_gen = 0;

// ---------------- helpers ----------------
__device__ __forceinline__ ull pack2(float w) {
    ull r; asm("mov.b64 %0, {%1, %1};" : "=l"(r) : "f"(w)); return r;
}
__device__ __forceinline__ void fma2(ull& d, ull a, ull b) {
    asm("fma.rn.f32x2 %0, %1, %2, %0;" : "+l"(d) : "l"(a), "l"(b));
}
__device__ __forceinline__ float hadd2(ull a) {
    float2 f = *reinterpret_cast<float2*>(&a); return f.x + f.y;
}
__device__ __forceinline__ void cpa16(uint32_t s, const float* g) {
    asm volatile("cp.async.cg.shared.global [%0], [%1], 16;" :: "r"(s), "l"(g) : "memory");
}
#define CPA_COMMIT() asm volatile("cp.async.commit_group;" ::: "memory")
#define CPA_WAIT1()  asm volatile("cp.async.wait_group 1;" ::: "memory")
#define CPA_WAIT0()  asm volatile("cp.async.wait_group 0;" ::: "memory")

// split fp32 into tf32 hi + tf32(lo) for 3xTF32 mma
__device__ __forceinline__ void tf32split(float v, uint32_t& hi, uint32_t& lo) {
    asm("cvt.rna.tf32.f32 %0, %1;" : "=r"(hi) : "f"(v));
    float l = v - __uint_as_float(hi);
    asm("cvt.rna.tf32.f32 %0, %1;" : "=r"(lo) : "f"(l));
}
// D += A(m16k8,tf32) * B(k8n8,tf32), fp32 accum
__device__ __forceinline__ void mma8(float* d, const uint32_t* a, const uint32_t* b) {
    asm("mma.sync.aligned.m16n8k8.row.col.f32.tf32.tf32.f32 "
        "{%0,%1,%2,%3}, {%4,%5,%6,%7}, {%8,%9}, {%0,%1,%2,%3};"
        : "+f"(d[0]), "+f"(d[1]), "+f"(d[2]), "+f"(d[3])
        : "r"(a[0]), "r"(a[1]), "r"(a[2]), "r"(a[3]), "r"(b[0]), "r"(b[1]));
}

__device__ __forceinline__ void gbar() {
    __syncthreads();
    if (threadIdx.x == 0) {
        __threadfence();
        unsigned gen = *(volatile unsigned*)&g_gen;
        if (atomicAdd(&g_cnt, 1u) == (unsigned)(gridDim.x - 1)) {
            g_cnt = 0;
            __threadfence();
            atomicAdd(&g_gen, 1u);
        } else {
            while (*(volatile unsigned*)&g_gen == gen) { __nanosleep(32); }
            __threadfence();
        }
    }
    __syncthreads();
}

__device__ __forceinline__ float bsum256(float v, float* sb) {
    int tx = threadIdx.x;
#pragma unroll
    for (int o = 16; o > 0; o >>= 1) v += __shfl_xor_sync(0xffffffffu, v, o);
    if ((tx & 31) == 0) sb[tx >> 5] = v;
    __syncthreads();
    float r = (tx < 8) ? sb[tx] : 0.f;
    if (tx < 32) {
#pragma unroll
        for (int o = 4; o > 0; o >>= 1) r += __shfl_xor_sync(0xffffffffu, r, o);
        if (tx == 0) sb[0] = r;
    }
    __syncthreads();
    r = sb[0];
    __syncthreads();
    return r;
}
__device__ __forceinline__ float bmax256(float v, float* sb) {
    int tx = threadIdx.x;
#pragma unroll
    for (int o = 16; o > 0; o >>= 1) v = fmaxf(v, __shfl_xor_sync(0xffffffffu, v, o));
    if ((tx & 31) == 0) sb[tx >> 5] = v;
    __syncthreads();
    float r = (tx < 8) ? sb[tx] : -3.0e38f;
    if (tx < 32) {
#pragma unroll
        for (int o = 4; o > 0; o >>= 1) r = fmaxf(r, __shfl_xor_sync(0xffffffffu, r, o));
        if (tx == 0) sb[0] = r;
    }
    __syncthreads();
    r = sb[0];
    __syncthreads();
    return r;
}

// jax threefry2x32, key=(0,42), partitionable: counter=(0,e), bits = o0^o1
__device__ __forceinline__ uint32_t rotl32(uint32_t x, int r) { return (x << r) | (x >> (32 - r)); }
__device__ __forceinline__ uint32_t threefry_xor(uint32_t c0, uint32_t c1) {
    const uint32_t ks0 = 0u, ks1 = 42u, ks2 = 0u ^ 42u ^ 0x1BD11BDAu;
    uint32_t x0 = c0 + ks0, x1 = c1 + ks1;
#define TF_R4(a,b,c,d) \
    x0 += x1; x1 = rotl32(x1,a); x1 ^= x0; \
    x0 += x1; x1 = rotl32(x1,b); x1 ^= x0; \
    x0 += x1; x1 = rotl32(x1,c); x1 ^= x0; \
    x0 += x1; x1 = rotl32(x1,d); x1 ^= x0;
    TF_R4(13,15,26,6)  x0 += ks1; x1 += ks2 + 1u;
    TF_R4(17,29,16,24) x0 += ks2; x1 += ks0 + 2u;
    TF_R4(13,15,26,6)  x0 += ks0; x1 += ks1 + 3u;
    TF_R4(17,29,16,24) x0 += ks1; x1 += ks2 + 4u;
    TF_R4(13,15,26,6)  x0 += ks2; x1 += ks0 + 5u;
#undef TF_R4
    return x0 ^ x1;
}
__device__ __forceinline__ float bits2normal(uint32_t bits) {
    uint32_t fb = (bits >> 9) | 0x3F800000u;
    float u01 = __uint_as_float(fb) - 1.0f;
    const float lo = -0.99999994f;
    float u = fmaf(u01, 1.99999994f, lo);
    u = fmaxf(lo, u);
    return 1.4142135623730951f * erfinvf(u);
}

// register-tiled FFMA consume (enc path)
__device__ __forceinline__ void consume4(ull* acc, const float4* w, const float* as,
                                         int kk, int boff) {
#pragma unroll
    for (int r = 0; r < 4; ++r) {
        const ulonglong2* ap = reinterpret_cast<const ulonglong2*>(&as[(kk + r) * B_ + boff]);
        ulonglong2 a01 = ap[0];
        ulonglong2 a23 = ap[1];
        const float* wf = reinterpret_cast<const float*>(&w[r]);
#pragma unroll
        for (int c = 0; c < 4; ++c) {
            ull wq = pack2(wf[c]);
            fma2(acc[c * 4 + 0], a01.x, wq);
            fma2(acc[c * 4 + 1], a01.y, wq);
            fma2(acc[c * 4 + 2], a23.x, wq);
            fma2(acc[c * 4 + 3], a23.y, wq);
        }
    }
}

// ---- 3xTF32 tensor-core split-K GEMM, 128-wide tiles ----
// pool: as[96][40] (hi after split), aslo[96][40], ws0[8][136], ws1[8][136]
#define AS_STRIDE 40
#define WS_STRIDE 136
#define ASLO_OFF  3840
#define WS0_OFF   7680
#define WS1_OFF   8768
// stage 8 k-rows x 128 cols of W
__device__ __forceinline__ void stage_w8(uint32_t wsaddr, const float* Wsrc, int N) {
    int i = threadIdx.x;           // 256 ops exactly
    int r = i >> 5, q = i & 31;
    cpa16(wsaddr + (uint32_t)(r * WS_STRIDE + q * 4) * 4, Wsrc + (size_t)r * N + q * 4);
}

__device__ void gemm_tf32(const float* __restrict__ A, const float* __restrict__ W,
                          float* __restrict__ P, int N, int ntiles, int KS, int Kper,
                          float* pool) {
    const int G = gridDim.x, tx = threadIdx.x;
    const int T = ntiles * KS;
    float* as = pool;
    uint32_t* asb = reinterpret_cast<uint32_t*>(pool);
    uint32_t* aslob = reinterpret_cast<uint32_t*>(pool + ASLO_OFF);
    float* wsb0 = pool + WS0_OFF;
    float* wsb1 = pool + WS1_OFF;
    uint32_t asa = (uint32_t)__cvta_generic_to_shared(as);
    uint32_t wsa0 = (uint32_t)__cvta_generic_to_shared(wsb0);
    uint32_t wsa1 = (uint32_t)__cvta_generic_to_shared(wsb1);
    const int w = tx >> 5, lane = tx & 31;
    const int g8 = lane >> 2, t4 = lane & 3;

    for (int t = blockIdx.x; t < T; t += G) {
        int tile = t % ntiles, ks = t / ntiles;
        int k0 = ks * Kper;
        // stage A (stride 40)
        for (int i = tx; i < Kper * 8; i += 256) {
            int k = i >> 3, q = i & 7;
            cpa16(asa + (uint32_t)(k * AS_STRIDE + q * 4) * 4, A + (size_t)(k0 + k) * B_ + q * 4);
        }
        CPA_COMMIT();
        CPA_WAIT0();
        __syncthreads();
        // pre-split A in place
        for (int i = tx; i < Kper * B_; i += 256) {
            int k = i >> 5, b = i & 31;
            int idx = k * AS_STRIDE + b;
            uint32_t hi, lo;
            tf32split(as[idx], hi, lo);
            asb[idx] = hi;
            aslob[idx] = lo;
        }
        stage_w8(wsa0, W + (size_t)k0 * N + tile * 128, N);
        CPA_COMMIT();
        __syncthreads();

        float acc[4][4];
#pragma unroll
        for (int nt = 0; nt < 4; ++nt)
#pragma unroll
            for (int j = 0; j < 4; ++j) acc[nt][j] = 0.f;

        int cur = 0;
        for (int kk = 0; kk < Kper; kk += 8) {
            if (kk + 8 < Kper) {
                stage_w8(cur ? wsa0 : wsa1, W + (size_t)(k0 + kk + 8) * N + tile * 128, N);
                CPA_COMMIT();
                CPA_WAIT1();
            } else {
                CPA_WAIT0();
            }
            __syncthreads();
            const float* ws = cur ? wsb1 : wsb0;
            uint32_t bhi[4][2], blo[4][2];
#pragma unroll
            for (int nt = 0; nt < 4; ++nt) {
                int i0 = (kk + t4) * AS_STRIDE + nt * 8 + g8;
                int i1 = (kk + t4 + 4) * AS_STRIDE + nt * 8 + g8;
                bhi[nt][0] = asb[i0]; blo[nt][0] = aslob[i0];
                bhi[nt][1] = asb[i1]; blo[nt][1] = aslob[i1];
            }
            int m0 = w * 16;
            float av[4];
            av[0] = ws[t4 * WS_STRIDE + m0 + g8];
            av[1] = ws[t4 * WS_STRIDE + m0 + g8 + 8];
            av[2] = ws[(t4 + 4) * WS_STRIDE + m0 + g8];
            av[3] = ws[(t4 + 4) * WS_STRIDE + m0 + g8 + 8];
            uint32_t ahi[4], alo[4];
#pragma unroll
            for (int j = 0; j < 4; ++j) tf32split(av[j], ahi[j], alo[j]);
#pragma unroll
            for (int nt = 0; nt < 4; ++nt) {
                mma8(acc[nt], ahi, bhi[nt]);
                mma8(acc[nt], ahi, blo[nt]);
                mma8(acc[nt], alo, bhi[nt]);
            }
            cur ^= 1;
            __syncthreads();
        }
#pragma unroll
        for (int nt = 0; nt < 4; ++nt) {
            int m = tile * 128 + w * 16 + g8;
            int b = nt * 8 + 2 * t4;
            float* dp = P + ((size_t)ks * N + m) * B_ + b;
            *reinterpret_cast<float2*>(dp) = make_float2(acc[nt][0], acc[nt][1]);
            *reinterpret_cast<float2*>(dp + 8 * B_) = make_float2(acc[nt][2], acc[nt][3]);
        }
    }
}

// ---------------- the persistent kernel ----------------
__global__ void __launch_bounds__(256, 2)
k_fused(const float* __restrict__ x, const float* __restrict__ prev_h,
        const float* __restrict__ trace, const float* __restrict__ bank,
        const float* __restrict__ W_enc, const float* __restrict__ b_enc,
        const float* __restrict__ gamma1, const float* __restrict__ beta1,
        const float* __restrict__ W_int, const float* __restrict__ b_int,
        const float* __restrict__ W_out, const float* __restrict__ b_out,
        const float* __restrict__ gamma2, const float* __restrict__ beta2,
        float* __restrict__ out) {
    __shared__ float pool[9856];          // 38.5 KB, aliased per phase
    __shared__ float sb[8];
    float* as = pool;
    const int tx = threadIdx.x;
    const int G = gridDim.x;
    const int cg = tx & 63, bh = tx >> 6, boff = bh * 8;

    // ---- P1: eff_mem transpose + em store + ssq (2048 tasks) + enc gemm (64 tasks) ----
    for (int t = blockIdx.x; t < 2048 + 4 * KS_ENC; t += G) {
        if (t < 2048) {
            int r = tx >> 3, c4 = (tx & 7) * 4;
            int m0 = (t & 63) * 32, h0 = (t >> 6) * 32;
            size_t base = (size_t)(m0 + r) * H_ + h0 + c4;
            float4 bv = *reinterpret_cast<const float4*>(bank + base);
            float4 tv = *reinterpret_cast<const float4*>(trace + base);
            float4 em;
            em.x = fmaf(0.5f, tv.x, bv.x); em.y = fmaf(0.5f, tv.y, bv.y);
            em.z = fmaf(0.5f, tv.z, bv.z); em.w = fmaf(0.5f, tv.w, bv.w);
            *reinterpret_cast<float4*>(&g_em[base]) = em;
            as[r * 33 + c4] = em.x; as[r * 33 + c4 + 1] = em.y;
            as[r * 33 + c4 + 2] = em.z; as[r * 33 + c4 + 3] = em.w;
            float ss = em.x * em.x + em.y * em.y + em.z * em.z + em.w * em.w;
#pragma unroll
            for (int o = 4; o > 0; o >>= 1) ss += __shfl_down_sync(0xffffffffu, ss, o, 8);
            if ((tx & 7) == 0) g_ssqp[(t >> 6) * M_ + m0 + r] = ss;
            __syncthreads();
            float4 o4;
            o4.x = as[(c4 + 0) * 33 + r]; o4.y = as[(c4 + 1) * 33 + r];
            o4.z = as[(c4 + 2) * 33 + r]; o4.w = as[(c4 + 3) * 33 + r];
            *reinterpret_cast<float4*>(&g_emT[(size_t)(h0 + r) * M_ + m0 + c4]) = o4;
            __syncthreads();
        } else {
            int q = t - 2048;
            int tile = q & 3, ks = q >> 2;
            int n = tile * 256 + cg * 4;
            int k0 = ks * 64;
            for (int i = tx; i < 64 * B_; i += 256) {
                int k = i >> 5, b = i & 31;
                as[k * B_ + b] = x[b * D_ + k0 + k];
            }
            __syncthreads();
            ull acc[16];
#pragma unroll
            for (int j = 0; j < 16; ++j) acc[j] = 0ull;
            const float* Wp = W_enc + (size_t)k0 * H_ + n;
            float4 wa[4], wb[4];
#pragma unroll
            for (int qq = 0; qq < 4; ++qq) wa[qq] = *reinterpret_cast<const float4*>(Wp + (size_t)qq * H_);
            for (int kk = 0; kk < 64; kk += 8) {
#pragma unroll
                for (int qq = 0; qq < 4; ++qq) wb[qq] = *reinterpret_cast<const float4*>(Wp + (size_t)(kk + 4 + qq) * H_);
                consume4(acc, wa, as, kk, boff);
                if (kk + 8 < 64) {
#pragma unroll
                    for (int qq = 0; qq < 4; ++qq) wa[qq] = *reinterpret_cast<const float4*>(Wp + (size_t)(kk + 8 + qq) * H_);
                }
                consume4(acc, wb, as, kk + 4, boff);
            }
            __syncthreads();
#pragma unroll
            for (int c = 0; c < 4; ++c) {
                ull* dst = reinterpret_cast<ull*>(g_encp + ((size_t)ks * H_ + n + c) * B_) + bh * 4;
                dst[0] = acc[c * 4 + 0]; dst[1] = acc[c * 4 + 1];
                dst[2] = acc[c * 4 + 2]; dst[3] = acc[c * 4 + 3];
            }
        }
    }
    gbar();

    // ---- P2a: reduce encp + bias + relu (128) + ssqred (8) ----
    for (int t = blockIdx.x; t < 136; t += G) {
        if (t < 128) {
            int idx = t * 256 + tx;
            int h = idx >> 5;
            float s = b_enc[h];
#pragma unroll
            for (int p = 0; p < KS_ENC; ++p) s += g_encp[p * (H_ * B_) + idx];
            g_zpre[idx] = fmaxf(s, 0.f);
        } else {
            int m = (t - 128) * 256 + tx;
            float s = 0.f;
#pragma unroll
            for (int j = 0; j < 32; ++j) s += g_ssqp[j * M_ + m];
            g_rss[m] = rsqrtf(fmaxf(s, 1e-12f));
        }
    }
    gbar();

    // ---- P2b: LN over h per batch (32) ----
    for (int t = blockIdx.x; t < 32; t += G) {
        int b = t;
        float v[4], ls = 0.f, lss = 0.f;
#pragma unroll
        for (int j = 0; j < 4; ++j) {
            int h = tx + j * 256;
            float s = g_zpre[h * B_ + b];
            v[j] = s; ls += s; lss += s * s;
        }
        float mean = bsum256(ls, sb) * (1.0f / H_);
        float msq  = bsum256(lss, sb) * (1.0f / H_);
        float rstd = rsqrtf(msq - mean * mean + 1e-6f);
        float zss = 0.f;
#pragma unroll
        for (int j = 0; j < 4; ++j) {
            int h = tx + j * 256;
            float z = (v[j] - mean) * rstd * gamma1[h] + beta1[h];
            g_comb[h * B_ + b] = z;
            zss += z * z;
            g_comb[(2048 + h) * B_ + b] = prev_h[b * H_ + h];
        }
        float zs = bsum256(zss, sb);
        if (tx == 0) g_zinv[b] = rsqrtf(fmaxf(zs, 1e-12f));
    }
    gbar();

    // ---- P3: sim gemm (16 tiles x 32 ks = 512 tasks, Kper=32, tensor) ----
    gemm_tf32(g_comb, g_emT, g_simp, 2048, 16, KS_SIM, 1024 / KS_SIM, pool);
    gbar();

    // ---- P4a: reduce simp + scale (256) ----
    for (int t = blockIdx.x; t < 256; t += G) {
        int idx = t * 256 + tx;
        int m = idx >> 5, b = idx & 31;
        float s = 0.f;
#pragma unroll
        for (int p = 0; p < KS_SIM; ++p) s += g_simp[p * (M_ * B_) + idx];
        g_sim[idx] = s * g_zinv[b] * g_rss[m] * (1.0f / 0.75f);
    }
    gbar();

    // ---- P4b: softmax (32) ----
    for (int t = blockIdx.x; t < 32; t += G) {
        int b = t;
        float s[8];
        float mx = -3.0e38f;
#pragma unroll
        for (int j = 0; j < 8; ++j) {
            int m = tx + j * 256;
            float v = g_sim[m * B_ + b];
            s[j] = v; mx = fmaxf(mx, v);
        }
        mx = bmax256(mx, sb);
        float sum = 0.f;
#pragma unroll
        for (int j = 0; j < 8; ++j) { s[j] = expf(s[j] - mx); sum += s[j]; }
        sum = bsum256(sum, sb);
        float inv = 1.0f / sum;
#pragma unroll
        for (int j = 0; j < 8; ++j) g_attn[(tx + j * 256) * B_ + b] = s[j] * inv;
    }
    gbar();

    // ---- P5: m_t gemm (8 tiles x 32 ks = 256 tasks, Kper=64, tensor) then trace (512 tasks) ----
    gemm_tf32(g_attn, g_em, g_mtp, 1024, 8, MS_MT, M_ / MS_MT, pool);
    for (int t = blockIdx.x; t < 512; t += G) {
        int h = (t & 3) * 256 + tx;
        int m0 = (t >> 2) * 8;
        __syncthreads();
        for (int i = tx; i < 16 * B_; i += 256) {
            int r = i >> 5, b = i & 31;
            int m = (r < 8) ? (m0 + r) : (1024 + m0 + r - 8);
            as[i] = g_attn[m * B_ + b];
        }
        __syncthreads();
        ull z2[16];
        const ull* zp = reinterpret_cast<const ull*>(&g_comb[h * B_]);
#pragma unroll
        for (int j = 0; j < 16; ++j) z2[j] = zp[j];
#pragma unroll 2
        for (int mi = 0; mi < 8; ++mi) {
            int m = m0 + mi;
            ull a0 = 0ull, a1 = 0ull;
            const ull* ap0 = reinterpret_cast<const ull*>(&as[mi * B_]);
            const ull* ap1 = reinterpret_cast<const ull*>(&as[(8 + mi) * B_]);
#pragma unroll
            for (int j = 0; j < 16; ++j) { fma2(a0, ap0[j], z2[j]); fma2(a1, ap1[j], z2[j]); }
            float s0v = hadd2(a0), s1v = hadd2(a1);
            uint32_t e0 = (uint32_t)(m * 1024 + h);
            uint32_t e1 = e0 + 1048576u;
            float n0 = bits2normal(threefry_xor(0u, e0)) * 0.001f;
            float n1 = bits2normal(threefry_xor(0u, e1)) * 0.001f;
            float t0v = trace[(size_t)m * H_ + h];
            float t1v = trace[(size_t)(m + 1024) * H_ + h];
            float r0 = t0v * 0.95f + 0.05f * (s0v * (1.0f / 32.0f) + n0);
            float r1 = t1v * 0.95f + 0.05f * (s1v * (1.0f / 32.0f) + n1);
            out[32768 + m * 1024 + h] = fminf(fmaxf(r0, -0.1f), 0.1f);
            out[32768 + (m + 1024) * 1024 + h] = fminf(fmaxf(r1, -0.1f), 0.1f);
        }
    }
    gbar();

    // ---- P6: reduce m_t partials (128) ----
    for (int t = blockIdx.x; t < 128; t += G) {
        int idx = t * 256 + tx;
        float s = 0.f;
#pragma unroll
        for (int p = 0; p < MS_MT; ++p) s += g_mtp[p * (H_ * B_) + idx];
        g_comb[H_ * B_ + idx] = s;
    }
    gbar();

    // ---- P7: int gemm (24 tiles x 32 ks = 768 tasks, Kper=96, tensor) ----
    gemm_tf32(g_comb, W_int, g_intp, 3072, 24, KS_INT, K3_ / KS_INT, pool);
    gbar();

    // ---- P8: intfin (384) ----
    for (int t = blockIdx.x; t < 384; t += G) {
        int idx = t * 256 + tx;
        int n = idx >> 5;
        float s = b_int[n];
#pragma unroll
        for (int p = 0; p < KS_INT; ++p) s += g_intp[p * (K3_ * B_) + idx];
        g_hid[idx] = fmaxf(s, 0.f);
    }
    gbar();

    // ---- P9: out gemm (8 tiles x 32 ks = 256 tasks, Kper=96, tensor) ----
    gemm_tf32(g_hid, W_out, g_outp, 1024, 8, KS_OUT, K3_ / KS_OUT, pool);
    gbar();

    // ---- P10a: reduce outp + bias + relu (128) ----
    for (int t = blockIdx.x; t < 128; t += G) {
        int idx = t * 256 + tx;
        int h = idx >> 5;
        float s = b_out[h];
#pragma unroll
        for (int p = 0; p < KS_OUT; ++p) s += g_outp[p * (H_ * B_) + idx];
        g_opre[idx] = fmaxf(s, 0.f);
    }
    gbar();

    // ---- P10b: LN -> h_t (32) ----
    for (int t = blockIdx.x; t < 32; t += G) {
        int b = t;
        float v[4], ls = 0.f, lss = 0.f;
#pragma unroll
        for (int j = 0; j < 4; ++j) {
            int h = tx + j * 256;
            float s = g_opre[h * B_ + b];
            v[j] = s; ls += s; lss += s * s;
        }
        float mean = bsum256(ls, sb) * (1.0f / H_);
        float msq  = bsum256(lss, sb) * (1.0f / H_);
        float rstd = rsqrtf(msq - mean * mean + 1e-6f);
#pragma unroll
        for (int j = 0; j < 4; ++j) {
            int h = tx + j * 256;
            out[b * H_ + h] = (v[j] - mean) * rstd * gamma2[h] + beta2[h];
        }
    }
}

// ---------------- launch ----------------
extern "C" void kernel_launch(void* const* d_in, const int* in_sizes, int n_in,
                              void* d_out, int out_size) {
    const float* x      = (const float*)d_in[0];
    const float* prev_h = (const float*)d_in[1];
    const float* trace  = (const float*)d_in[2];
    const float* bank   = (const float*)d_in[3];
    const float* W_enc  = (const float*)d_in[4];
    const float* b_enc  = (const float*)d_in[5];
    const float* gamma1 = (const float*)d_in[6];
    const float* beta1  = (const float*)d_in[7];
    const float* W_int  = (const float*)d_in[8];
    const float* b_int  = (const float*)d_in[9];
    const float* W_out  = (const float*)d_in[10];
    const float* b_out  = (const float*)d_in[11];
    const float* gamma2 = (const float*)d_in[12];
    const float* beta2  = (const float*)d_in[13];
    float* out = (float*)d_out;

    k_fused<<<GRID_, 256>>>(x, prev_h, trace, bank, W_enc, b_enc, gamma1, beta1,
                            W_int, b_int, W_out, b_out, gamma2, beta2, out);
}